// round 9
// baseline (speedup 1.0000x reference)
#include <cuda_runtime.h>

// Problem constants (match reference)
#define B   16
#define LX  2048
#define LR  1024
#define D   768
#define T   (LX + LR + 3)   // 3075
#define D4  (D / 4)         // 192 float4 per row
#define RPB 8               // rows per CTA (B*T = 49200 divisible by 8)

// out[b,t,:] =
//   t == 0                          : CLS
//   1 <= t <= lx[b]                 : X[b, t-1]
//   t == lx[b]+1                    : RING
//   lx[b]+2 <= t < lx[b]+2+lr[b]    : Xr[b, t-lx[b]-2]
//   t == lx[b]+lr[b]+2              : END
//   else                            : 0
//
// Champion structure (R2): 192 threads, one float4/thread/row, streaming
// cache hints both sides. R9 change: RPB 4 -> 8 for longer contiguous
// per-CTA output spans (24KB) -> better DRAM page locality, fewer CTAs.
// All 8 row-gathers are issued before any store (MLP=8).
__global__ __launch_bounds__(D4) void assemble_kernel(
    const float4* __restrict__ X,
    const float4* __restrict__ Xr,
    const float4* __restrict__ CLS,
    const float4* __restrict__ RING,
    const float4* __restrict__ END,
    const int*    __restrict__ lx,
    const int*    __restrict__ lr,
    float4*       __restrict__ out)
{
    const int c    = threadIdx.x;            // 0..191
    const int row0 = blockIdx.x * RPB;       // first of RPB consecutive rows

    // All RPB rows of one CTA share the same batch index except possibly at a
    // batch boundary; compute b/t per row (const-div -> mul/shift, cheap).
    float4 v[RPB];

    #pragma unroll
    for (int i = 0; i < RPB; i++) {
        const int row = row0 + i;
        const int b   = row / T;
        const int t   = row - b * T;

        const int lxb = __ldg(&lx[b]);
        const int lrb = __ldg(&lr[b]);

        if (t == 0) {
            v[i] = CLS[c];
        } else if (t <= lxb) {
            v[i] = __ldcs(&X[((long)b * LX + (t - 1)) * D4 + c]);
        } else if (t == lxb + 1) {
            v[i] = RING[c];
        } else if (t < lxb + 2 + lrb) {
            v[i] = __ldcs(&Xr[((long)b * LR + (t - lxb - 2)) * D4 + c]);
        } else if (t == lxb + lrb + 2) {
            v[i] = END[c];
        } else {
            v[i] = make_float4(0.f, 0.f, 0.f, 0.f);
        }
    }

    #pragma unroll
    for (int i = 0; i < RPB; i++) {
        __stcs(&out[(long)(row0 + i) * D4 + c], v[i]);
    }
}

extern "C" void kernel_launch(void* const* d_in, const int* in_sizes, int n_in,
                              void* d_out, int out_size)
{
    const float4* X    = (const float4*)d_in[0];
    const float4* Xr   = (const float4*)d_in[1];
    const float4* CLS  = (const float4*)d_in[2];
    const float4* RING = (const float4*)d_in[3];
    const float4* END  = (const float4*)d_in[4];
    const int*    lx   = (const int*)d_in[5];
    const int*    lr   = (const int*)d_in[6];
    float4*       out  = (float4*)d_out;

    dim3 grid((B * T) / RPB);   // 6150 CTAs
    dim3 block(D4);             // 192 threads
    assemble_kernel<<<grid, block>>>(X, Xr, CLS, RING, END, lx, lr, out);
}

// round 10
// speedup vs baseline: 1.1481x; 1.1481x over previous
#include <cuda_runtime.h>
#include <cstdint>

// Problem constants (match reference)
#define B   16
#define LX  2048
#define LR  1024
#define D   768
#define T   (LX + LR + 3)   // 3075
#define D4  (D / 4)         // 192 float4 per row
#define RPB 4               // rows per CTA (B*T divisible by 4)

// out[b,t,:] =
//   t == 0                          : CLS
//   1 <= t <= lx[b]                 : X[b, t-1]
//   t == lx[b]+1                    : RING
//   lx[b]+2 <= t < lx[b]+2+lr[b]    : Xr[b, t-lx[b]-2]
//   t == lx[b]+lr[b]+2              : END
//   else                            : 0
//
// R10: write path via bulk async store. Each CTA gathers its 4 contiguous
// rows (12KB) into SMEM, then one thread issues a single
// cp.async.bulk.global.shared::cta for the whole span. Large ordered write
// bursts -> better DRAM write efficiency; stores bypass L1tex; fewer live
// registers -> higher occupancy. Reads keep the streaming (__ldcs) policy.

__device__ __forceinline__ uint32_t smem_u32(const void* p) {
    uint32_t a;
    asm("{ .reg .u64 t; cvta.to.shared.u64 t, %1; cvt.u32.u64 %0, t; }"
        : "=r"(a) : "l"(p));
    return a;
}

__global__ __launch_bounds__(D4) void assemble_kernel(
    const float4* __restrict__ X,
    const float4* __restrict__ Xr,
    const float4* __restrict__ CLS,
    const float4* __restrict__ RING,
    const float4* __restrict__ END,
    const int*    __restrict__ lx,
    const int*    __restrict__ lr,
    float4*       __restrict__ out)
{
    __shared__ __align__(128) float4 buf[RPB * D4];   // 12 KB

    const int c    = threadIdx.x;            // 0..191
    const int row0 = blockIdx.x * RPB;

    #pragma unroll
    for (int i = 0; i < RPB; i++) {
        const int row = row0 + i;
        const int b   = row / T;              // const-div -> mul/shift
        const int t   = row - b * T;

        const int lxb = __ldg(&lx[b]);
        const int lrb = __ldg(&lr[b]);

        float4 v;
        if (t == 0) {
            v = CLS[c];
        } else if (t <= lxb) {
            v = __ldcs(&X[((long)b * LX + (t - 1)) * D4 + c]);
        } else if (t == lxb + 1) {
            v = RING[c];
        } else if (t < lxb + 2 + lrb) {
            v = __ldcs(&Xr[((long)b * LR + (t - lxb - 2)) * D4 + c]);
        } else if (t == lxb + lrb + 2) {
            v = END[c];
        } else {
            v = make_float4(0.f, 0.f, 0.f, 0.f);
        }
        buf[i * D4 + c] = v;
    }

    __syncthreads();

    if (threadIdx.x == 0) {
        // Make generic-proxy STS visible to the async proxy, then issue one
        // 12KB bulk store covering the CTA's 4 contiguous output rows.
        asm volatile("fence.proxy.async.shared::cta;" ::: "memory");
        const uint32_t saddr = smem_u32(buf);
        asm volatile(
            "cp.async.bulk.global.shared::cta.bulk_group [%0], [%1], %2;"
            :: "l"(out + (long)row0 * D4), "r"(saddr), "n"(RPB * D4 * 16)
            : "memory");
        asm volatile("cp.async.bulk.commit_group;" ::: "memory");
        asm volatile("cp.async.bulk.wait_group 0;" ::: "memory");
    }
}

extern "C" void kernel_launch(void* const* d_in, const int* in_sizes, int n_in,
                              void* d_out, int out_size)
{
    const float4* X    = (const float4*)d_in[0];
    const float4* Xr   = (const float4*)d_in[1];
    const float4* CLS  = (const float4*)d_in[2];
    const float4* RING = (const float4*)d_in[3];
    const float4* END  = (const float4*)d_in[4];
    const int*    lx   = (const int*)d_in[5];
    const int*    lr   = (const int*)d_in[6];
    float4*       out  = (float4*)d_out;

    dim3 grid((B * T) / RPB);   // 12300 CTAs
    dim3 block(D4);             // 192 threads
    assemble_kernel<<<grid, block>>>(X, Xr, CLS, RING, END, lx, lr, out);
}

// round 11
// speedup vs baseline: 1.1580x; 1.0086x over previous
#include <cuda_runtime.h>

// Problem constants (match reference)
#define B   16
#define LX  2048
#define LR  1024
#define D   768
#define T   (LX + LR + 3)   // 3075
#define D4  (D / 4)         // 192 float4 per row
#define RPB 4               // rows per CTA (B*T = 49200 divisible by 4)

// out[b,t,:] =
//   t == 0                          : CLS
//   1 <= t <= lx[b]                 : X[b, t-1]
//   t == lx[b]+1                    : RING
//   lx[b]+2 <= t < lx[b]+2+lr[b]    : Xr[b, t-lx[b]-2]
//   t == lx[b]+lr[b]+2              : END
//   else                            : 0
//
// Cache policy (R11): reads use DEFAULT (evict-normal) policy so the ~75MB
// gather working set can stay L2-resident across graph replays; the 151MB
// output stream is marked evict-first (__stcs) so it self-displaces instead
// of washing out the read set. (All prior combos either evicted the reads
// eagerly or let the write flood through at normal priority.)
__global__ __launch_bounds__(D4) void assemble_kernel(
    const float4* __restrict__ X,
    const float4* __restrict__ Xr,
    const float4* __restrict__ CLS,
    const float4* __restrict__ RING,
    const float4* __restrict__ END,
    const int*    __restrict__ lx,
    const int*    __restrict__ lr,
    float4*       __restrict__ out)
{
    const int c    = threadIdx.x;            // 0..191
    const int row0 = blockIdx.x * RPB;       // first of RPB consecutive rows

    float4 v[RPB];

    #pragma unroll
    for (int i = 0; i < RPB; i++) {
        const int row = row0 + i;
        const int b   = row / T;              // const-div -> mul/shift
        const int t   = row - b * T;

        const int lxb = __ldg(&lx[b]);
        const int lrb = __ldg(&lr[b]);

        if (t == 0) {
            v[i] = CLS[c];
        } else if (t <= lxb) {
            v[i] = X[((long)b * LX + (t - 1)) * D4 + c];        // default policy
        } else if (t == lxb + 1) {
            v[i] = RING[c];
        } else if (t < lxb + 2 + lrb) {
            v[i] = Xr[((long)b * LR + (t - lxb - 2)) * D4 + c]; // default policy
        } else if (t == lxb + lrb + 2) {
            v[i] = END[c];
        } else {
            v[i] = make_float4(0.f, 0.f, 0.f, 0.f);
        }
    }

    #pragma unroll
    for (int i = 0; i < RPB; i++) {
        __stcs(&out[(long)(row0 + i) * D4 + c], v[i]);          // evict-first stream
    }
}

extern "C" void kernel_launch(void* const* d_in, const int* in_sizes, int n_in,
                              void* d_out, int out_size)
{
    const float4* X    = (const float4*)d_in[0];
    const float4* Xr   = (const float4*)d_in[1];
    const float4* CLS  = (const float4*)d_in[2];
    const float4* RING = (const float4*)d_in[3];
    const float4* END  = (const float4*)d_in[4];
    const int*    lx   = (const int*)d_in[5];
    const int*    lr   = (const int*)d_in[6];
    float4*       out  = (float4*)d_out;

    dim3 grid((B * T) / RPB);   // 12300 CTAs
    dim3 block(D4);             // 192 threads
    assemble_kernel<<<grid, block>>>(X, Xr, CLS, RING, END, lx, lr, out);
}

// round 12
// speedup vs baseline: 1.2088x; 1.0439x over previous
#include <cuda_runtime.h>

// Problem constants (match reference)
#define B   16
#define LX  2048
#define LR  1024
#define D   768
#define T   (LX + LR + 3)   // 3075
#define D4  (D / 4)         // 192 float4 per row
#define RPB 4               // rows per CTA (B*T = 49200 divisible by 4)
#define TPB 256             // 8 warps -> 32 warps/SM at 4 CTAs (100% theoretical occ)
#define CPB (RPB * D4)      // 768 chunks per CTA
#define KPT (CPB / TPB)     // 3 chunks per thread

// out[b,t,:] =
//   t == 0                          : CLS
//   1 <= t <= lx[b]                 : X[b, t-1]
//   t == lx[b]+1                    : RING
//   lx[b]+2 <= t < lx[b]+2+lr[b]    : Xr[b, t-lx[b]-2]
//   t == lx[b]+lr[b]+2              : END
//   else                            : 0
//
// Champion policy (measured best): streaming on both sides (__ldcs/__stcs);
// working set 226MB > 126MB L2, nothing retainable across graph replays.
// Structure: 256-thread CTAs, flat chunk indexing over 4 contiguous rows.
// 192 % 32 == 0 so each warp's 32 consecutive chunks sit in ONE row ->
// warp-uniform branching, fully coalesced 128B accesses.
__global__ __launch_bounds__(TPB) void assemble_kernel(
    const float4* __restrict__ X,
    const float4* __restrict__ Xr,
    const float4* __restrict__ CLS,
    const float4* __restrict__ RING,
    const float4* __restrict__ END,
    const int*    __restrict__ lx,
    const int*    __restrict__ lr,
    float4*       __restrict__ out)
{
    const int  tid   = threadIdx.x;
    const long base  = (long)blockIdx.x * CPB;   // first chunk of this CTA

    float4 v[KPT];

    #pragma unroll
    for (int k = 0; k < KPT; k++) {
        const int chunk = tid + k * TPB;          // 0..767
        const int rl    = chunk / D4;             // row within CTA (0..3)
        const int c     = chunk - rl * D4;        // 0..191
        const int row   = blockIdx.x * RPB + rl;
        const int b     = row / T;                // const-div -> mul/shift
        const int t     = row - b * T;

        const int lxb = __ldg(&lx[b]);
        const int lrb = __ldg(&lr[b]);

        if (t == 0) {
            v[k] = CLS[c];
        } else if (t <= lxb) {
            v[k] = __ldcs(&X[((long)b * LX + (t - 1)) * D4 + c]);
        } else if (t == lxb + 1) {
            v[k] = RING[c];
        } else if (t < lxb + 2 + lrb) {
            v[k] = __ldcs(&Xr[((long)b * LR + (t - lxb - 2)) * D4 + c]);
        } else if (t == lxb + lrb + 2) {
            v[k] = END[c];
        } else {
            v[k] = make_float4(0.f, 0.f, 0.f, 0.f);
        }
    }

    #pragma unroll
    for (int k = 0; k < KPT; k++) {
        __stcs(&out[base + tid + k * TPB], v[k]);
    }
}

extern "C" void kernel_launch(void* const* d_in, const int* in_sizes, int n_in,
                              void* d_out, int out_size)
{
    const float4* X    = (const float4*)d_in[0];
    const float4* Xr   = (const float4*)d_in[1];
    const float4* CLS  = (const float4*)d_in[2];
    const float4* RING = (const float4*)d_in[3];
    const float4* END  = (const float4*)d_in[4];
    const int*    lx   = (const int*)d_in[5];
    const int*    lr   = (const int*)d_in[6];
    float4*       out  = (float4*)d_out;

    dim3 grid((B * T) / RPB);   // 12300 CTAs
    dim3 block(TPB);            // 256 threads
    assemble_kernel<<<grid, block>>>(X, Xr, CLS, RING, END, lx, lr, out);
}